// round 1
// baseline (speedup 1.0000x reference)
#include <cuda_runtime.h>

#define D_MODEL 1024
#define NHEADS 16
#define DK 64
#define BATCH 2
#define SEQ 2048
#define MROWS (BATCH*SEQ)

// Scratch (allocation-free rule: __device__ globals)
__device__ float g_Q[MROWS * D_MODEL];
__device__ float g_K[MROWS * D_MODEL];
__device__ float g_V[MROWS * D_MODEL];
__device__ float g_X[MROWS * D_MODEL];

// ----------------------------------------------------------------------------
// GEMM: Y[M,N] = X[M,K] @ W[N,K]^T + bias[N]   (torch Linear)
// BM=128, BN=64, BK=16, 256 threads, 8x4 per-thread microtile.
// ----------------------------------------------------------------------------
#define BM 128
#define BN 64
#define BK 16

__global__ __launch_bounds__(256, 2) void gemm_bias(
    const float* __restrict__ X, const float* __restrict__ W,
    const float* __restrict__ bias, float* __restrict__ Y,
    int M, int N, int K)
{
    __shared__ float Xs[BK][BM];
    __shared__ float Ws[BK][BN];
    const int tid = threadIdx.x;
    const int m0 = blockIdx.y * BM;
    const int n0 = blockIdx.x * BN;
    const int ty = tid >> 4;   // 0..15 (m)
    const int tx = tid & 15;   // 0..15 (n)

    float acc[8][4];
#pragma unroll
    for (int i = 0; i < 8; i++)
#pragma unroll
        for (int j = 0; j < 4; j++) acc[i][j] = 0.f;

    for (int kt = 0; kt < K; kt += BK) {
        // Load X tile (128x16) transposed into Xs[k][m]
#pragma unroll
        for (int t = 0; t < 2; t++) {
            int i = tid + t * 256;           // 0..511 float4s
            int r = i >> 2;                  // 0..127
            int kq = (i & 3) << 2;           // 0,4,8,12
            float4 v = *(const float4*)(X + (long)(m0 + r) * K + kt + kq);
            Xs[kq + 0][r] = v.x; Xs[kq + 1][r] = v.y;
            Xs[kq + 2][r] = v.z; Xs[kq + 3][r] = v.w;
        }
        // Load W tile (64x16) transposed into Ws[k][n]
        {
            int r = tid >> 2;                // 0..63
            int kq = (tid & 3) << 2;
            float4 v = *(const float4*)(W + (long)(n0 + r) * K + kt + kq);
            Ws[kq + 0][r] = v.x; Ws[kq + 1][r] = v.y;
            Ws[kq + 2][r] = v.z; Ws[kq + 3][r] = v.w;
        }
        __syncthreads();

#pragma unroll
        for (int k = 0; k < BK; k++) {
            float a[8], b[4];
            *(float4*)&a[0] = *(const float4*)&Xs[k][ty * 8];
            *(float4*)&a[4] = *(const float4*)&Xs[k][ty * 8 + 4];
            *(float4*)&b[0] = *(const float4*)&Ws[k][tx * 4];
#pragma unroll
            for (int i = 0; i < 8; i++)
#pragma unroll
                for (int j = 0; j < 4; j++)
                    acc[i][j] = fmaf(a[i], b[j], acc[i][j]);
        }
        __syncthreads();
    }

    float4 bv = *(const float4*)(bias + n0 + tx * 4);
#pragma unroll
    for (int i = 0; i < 8; i++) {
        float4 o;
        o.x = acc[i][0] + bv.x;
        o.y = acc[i][1] + bv.y;
        o.z = acc[i][2] + bv.z;
        o.w = acc[i][3] + bv.w;
        *(float4*)(Y + (long)(m0 + ty * 8 + i) * N + n0 + tx * 4) = o;
    }
}

// ----------------------------------------------------------------------------
// Flash attention, fp32, causal. One CTA per (b, h, 64-row q tile).
// 256 threads as 16x16 grid; each thread owns 4 q-rows x 4 cols.
// ----------------------------------------------------------------------------
#define PST 68                         // padded row stride (floats), 16B-aligned
#define SMEM_ATTN ((3 * 64 * PST + 64 * 64) * 4)

__global__ __launch_bounds__(256, 1) void attn_kernel()
{
    extern __shared__ float sm[];
    float* QsT = sm;                   // [64 d][PST rows]
    float* KsT = sm + 64 * PST;        // [64 d][PST kcols]
    float* PsT = sm + 2 * 64 * PST;    // [64 k][PST rows]
    float* Vs  = sm + 3 * 64 * PST;    // [64 k][64 d]

    const int tid = threadIdx.x;
    const int qt  = (int)(gridDim.x - 1 - blockIdx.x);  // heavy tiles first
    const int h   = blockIdx.y;
    const int b   = blockIdx.z;
    const int q0  = qt * 64;
    const int tx  = tid & 15;          // score k-col group / output d group
    const int ty  = tid >> 4;          // q-row group

    const float* Qb = g_Q + ((long)b * SEQ) * D_MODEL + h * DK;
    const float* Kb = g_K + ((long)b * SEQ) * D_MODEL + h * DK;
    const float* Vb = g_V + ((long)b * SEQ) * D_MODEL + h * DK;
    float*       Xb = g_X + ((long)b * SEQ) * D_MODEL + h * DK;

    // Load Q tile transposed: QsT[d][r]
#pragma unroll
    for (int t = 0; t < 4; t++) {
        int i = tid + t * 256;         // 1024 float4s total for 64x64
        int r = i >> 4;                // 0..63
        int d4 = (i & 15) << 2;        // 0..60
        float4 v = *(const float4*)(Qb + (long)(q0 + r) * D_MODEL + d4);
        QsT[(d4 + 0) * PST + r] = v.x;
        QsT[(d4 + 1) * PST + r] = v.y;
        QsT[(d4 + 2) * PST + r] = v.z;
        QsT[(d4 + 3) * PST + r] = v.w;
    }

    float m_i[4], l_i[4], o[4][4];
#pragma unroll
    for (int i = 0; i < 4; i++) {
        m_i[i] = -1e30f; l_i[i] = 0.f;
#pragma unroll
        for (int j = 0; j < 4; j++) o[i][j] = 0.f;
    }

    const int nkt = qt + 1;            // causal: only k-tiles with k0 <= q0
    for (int kt = 0; kt < nkt; kt++) {
        const int k0 = kt * 64;
        __syncthreads();               // guard smem reuse (also covers Q load)
#pragma unroll
        for (int t = 0; t < 4; t++) {
            int i = tid + t * 256;
            int r = i >> 4;
            int d4 = (i & 15) << 2;
            float4 kv = *(const float4*)(Kb + (long)(k0 + r) * D_MODEL + d4);
            KsT[(d4 + 0) * PST + r] = kv.x;
            KsT[(d4 + 1) * PST + r] = kv.y;
            KsT[(d4 + 2) * PST + r] = kv.z;
            KsT[(d4 + 3) * PST + r] = kv.w;
            float4 vv = *(const float4*)(Vb + (long)(k0 + r) * D_MODEL + d4);
            *(float4*)&Vs[r * 64 + d4] = vv;
        }
        __syncthreads();

        // Scores: s[i][j] = Q[q0+ty*4+i] . K[k0+tx*4+j]
        float s[4][4];
#pragma unroll
        for (int i = 0; i < 4; i++)
#pragma unroll
            for (int j = 0; j < 4; j++) s[i][j] = 0.f;
#pragma unroll 8
        for (int d = 0; d < DK; d++) {
            float4 qa = *(const float4*)&QsT[d * PST + ty * 4];
            float4 kb = *(const float4*)&KsT[d * PST + tx * 4];
            s[0][0] = fmaf(qa.x, kb.x, s[0][0]); s[0][1] = fmaf(qa.x, kb.y, s[0][1]);
            s[0][2] = fmaf(qa.x, kb.z, s[0][2]); s[0][3] = fmaf(qa.x, kb.w, s[0][3]);
            s[1][0] = fmaf(qa.y, kb.x, s[1][0]); s[1][1] = fmaf(qa.y, kb.y, s[1][1]);
            s[1][2] = fmaf(qa.y, kb.z, s[1][2]); s[1][3] = fmaf(qa.y, kb.w, s[1][3]);
            s[2][0] = fmaf(qa.z, kb.x, s[2][0]); s[2][1] = fmaf(qa.z, kb.y, s[2][1]);
            s[2][2] = fmaf(qa.z, kb.z, s[2][2]); s[2][3] = fmaf(qa.z, kb.w, s[2][3]);
            s[3][0] = fmaf(qa.w, kb.x, s[3][0]); s[3][1] = fmaf(qa.w, kb.y, s[3][1]);
            s[3][2] = fmaf(qa.w, kb.z, s[3][2]); s[3][3] = fmaf(qa.w, kb.w, s[3][3]);
        }

        const float scale = 0.125f;    // 1/sqrt(64)
#pragma unroll
        for (int i = 0; i < 4; i++)
#pragma unroll
            for (int j = 0; j < 4; j++) s[i][j] *= scale;

        if (kt == qt) {                // only the diagonal tile is partial
#pragma unroll
            for (int i = 0; i < 4; i++) {
                int qr = ty * 4 + i;
#pragma unroll
                for (int j = 0; j < 4; j++)
                    if (tx * 4 + j > qr) s[i][j] = -1e30f;
            }
        }

        // Online softmax per q-row (16-thread row group via shfl width 16)
#pragma unroll
        for (int i = 0; i < 4; i++) {
            float t0 = fmaxf(fmaxf(s[i][0], s[i][1]), fmaxf(s[i][2], s[i][3]));
#pragma unroll
            for (int off = 8; off > 0; off >>= 1)
                t0 = fmaxf(t0, __shfl_xor_sync(0xffffffffu, t0, off, 16));
            float m_new = fmaxf(m_i[i], t0);
            float alpha = __expf(m_i[i] - m_new);
            float rs = 0.f;
#pragma unroll
            for (int j = 0; j < 4; j++) {
                s[i][j] = __expf(s[i][j] - m_new);
                rs += s[i][j];
            }
#pragma unroll
            for (int off = 8; off > 0; off >>= 1)
                rs += __shfl_xor_sync(0xffffffffu, rs, off, 16);
            l_i[i] = l_i[i] * alpha + rs;
#pragma unroll
            for (int j = 0; j < 4; j++) o[i][j] *= alpha;
            m_i[i] = m_new;
        }

        // Store P transposed: PsT[k][r]   (producer/consumer within same warp)
#pragma unroll
        for (int j = 0; j < 4; j++)
#pragma unroll
            for (int i = 0; i < 4; i++)
                PsT[(tx * 4 + j) * PST + ty * 4 + i] = s[i][j];
        __syncwarp();

        // O += P @ V
#pragma unroll 8
        for (int kk = 0; kk < 64; kk++) {
            float4 pa = *(const float4*)&PsT[kk * PST + ty * 4];
            float4 vb = *(const float4*)&Vs[kk * 64 + tx * 4];
            o[0][0] = fmaf(pa.x, vb.x, o[0][0]); o[0][1] = fmaf(pa.x, vb.y, o[0][1]);
            o[0][2] = fmaf(pa.x, vb.z, o[0][2]); o[0][3] = fmaf(pa.x, vb.w, o[0][3]);
            o[1][0] = fmaf(pa.y, vb.x, o[1][0]); o[1][1] = fmaf(pa.y, vb.y, o[1][1]);
            o[1][2] = fmaf(pa.y, vb.z, o[1][2]); o[1][3] = fmaf(pa.y, vb.w, o[1][3]);
            o[2][0] = fmaf(pa.z, vb.x, o[2][0]); o[2][1] = fmaf(pa.z, vb.y, o[2][1]);
            o[2][2] = fmaf(pa.z, vb.z, o[2][2]); o[2][3] = fmaf(pa.z, vb.w, o[2][3]);
            o[3][0] = fmaf(pa.w, vb.x, o[3][0]); o[3][1] = fmaf(pa.w, vb.y, o[3][1]);
            o[3][2] = fmaf(pa.w, vb.z, o[3][2]); o[3][3] = fmaf(pa.w, vb.w, o[3][3]);
        }
    }

    // Normalize + write x[b, s, h*64 + d]
#pragma unroll
    for (int i = 0; i < 4; i++) {
        float inv = 1.f / l_i[i];
        float4 ov;
        ov.x = o[i][0] * inv; ov.y = o[i][1] * inv;
        ov.z = o[i][2] * inv; ov.w = o[i][3] * inv;
        *(float4*)(Xb + (long)(q0 + ty * 4 + i) * D_MODEL + tx * 4) = ov;
    }
}

// ----------------------------------------------------------------------------
extern "C" void kernel_launch(void* const* d_in, const int* in_sizes, int n_in,
                              void* d_out, int out_size)
{
    const float* q   = (const float*)d_in[0];
    const float* k   = (const float*)d_in[1];
    const float* v   = (const float*)d_in[2];
    // d_in[3] = mask (int32 tril) — causal handled analytically
    const float* w_q = (const float*)d_in[4];
    const float* b_q = (const float*)d_in[5];
    const float* w_k = (const float*)d_in[6];
    const float* b_k = (const float*)d_in[7];
    const float* w_v = (const float*)d_in[8];
    const float* b_v = (const float*)d_in[9];
    const float* w_o = (const float*)d_in[10];
    const float* b_o = (const float*)d_in[11];
    float* out = (float*)d_out;

    float *pQ, *pK, *pV, *pX;
    cudaGetSymbolAddress((void**)&pQ, g_Q);
    cudaGetSymbolAddress((void**)&pK, g_K);
    cudaGetSymbolAddress((void**)&pV, g_V);
    cudaGetSymbolAddress((void**)&pX, g_X);

    dim3 ggrid(D_MODEL / BN, MROWS / BM);   // (16, 32)
    gemm_bias<<<ggrid, 256>>>(q, w_q, b_q, pQ, MROWS, D_MODEL, D_MODEL);
    gemm_bias<<<ggrid, 256>>>(k, w_k, b_k, pK, MROWS, D_MODEL, D_MODEL);
    gemm_bias<<<ggrid, 256>>>(v, w_v, b_v, pV, MROWS, D_MODEL, D_MODEL);

    cudaFuncSetAttribute(attn_kernel,
                         cudaFuncAttributeMaxDynamicSharedMemorySize, SMEM_ATTN);
    dim3 agrid(SEQ / 64, NHEADS, BATCH);    // (32, 16, 2)
    attn_kernel<<<agrid, 256, SMEM_ATTN>>>();

    gemm_bias<<<ggrid, 256>>>(pX, w_o, b_o, out, MROWS, D_MODEL, D_MODEL);
}

// round 2
// speedup vs baseline: 1.0022x; 1.0022x over previous
#include <cuda_runtime.h>

#define D_MODEL 1024
#define NHEADS 16
#define DK 64
#define BATCH 2
#define SEQ 2048
#define MROWS (BATCH*SEQ)

// Scratch (allocation-free rule: __device__ globals)
__device__ float g_Q[MROWS * D_MODEL];
__device__ float g_K[MROWS * D_MODEL];
__device__ float g_V[MROWS * D_MODEL];
__device__ float g_X[MROWS * D_MODEL];

// ----------------------------------------------------------------------------
// GEMM: Y[M,N] = X[M,K] @ W[N,K]^T + bias[N]   (torch Linear)
// BM=128, BN=64, BK=16, 256 threads, 8x4 per-thread microtile.
// ----------------------------------------------------------------------------
#define BM 128
#define BN 64
#define BK 16

__global__ __launch_bounds__(256, 2) void gemm_bias(
    const float* __restrict__ X, const float* __restrict__ W,
    const float* __restrict__ bias, float* __restrict__ Y,
    int M, int N, int K)
{
    __shared__ float Xs[BK][BM];
    __shared__ float Ws[BK][BN];
    const int tid = threadIdx.x;
    const int m0 = blockIdx.y * BM;
    const int n0 = blockIdx.x * BN;
    const int ty = tid >> 4;   // 0..15 (m)
    const int tx = tid & 15;   // 0..15 (n)

    float acc[8][4];
#pragma unroll
    for (int i = 0; i < 8; i++)
#pragma unroll
        for (int j = 0; j < 4; j++) acc[i][j] = 0.f;

    for (int kt = 0; kt < K; kt += BK) {
        // Load X tile (128x16) transposed into Xs[k][m]
#pragma unroll
        for (int t = 0; t < 2; t++) {
            int i = tid + t * 256;           // 0..511 float4s
            int r = i >> 2;                  // 0..127
            int kq = (i & 3) << 2;           // 0,4,8,12
            float4 v = *(const float4*)(X + (long)(m0 + r) * K + kt + kq);
            Xs[kq + 0][r] = v.x; Xs[kq + 1][r] = v.y;
            Xs[kq + 2][r] = v.z; Xs[kq + 3][r] = v.w;
        }
        // Load W tile (64x16) transposed into Ws[k][n]
        {
            int r = tid >> 2;                // 0..63
            int kq = (tid & 3) << 2;
            float4 v = *(const float4*)(W + (long)(n0 + r) * K + kt + kq);
            Ws[kq + 0][r] = v.x; Ws[kq + 1][r] = v.y;
            Ws[kq + 2][r] = v.z; Ws[kq + 3][r] = v.w;
        }
        __syncthreads();

#pragma unroll
        for (int k = 0; k < BK; k++) {
            float a[8], b[4];
            *(float4*)&a[0] = *(const float4*)&Xs[k][ty * 8];
            *(float4*)&a[4] = *(const float4*)&Xs[k][ty * 8 + 4];
            *(float4*)&b[0] = *(const float4*)&Ws[k][tx * 4];
#pragma unroll
            for (int i = 0; i < 8; i++)
#pragma unroll
                for (int j = 0; j < 4; j++)
                    acc[i][j] = fmaf(a[i], b[j], acc[i][j]);
        }
        __syncthreads();
    }

    float4 bv = *(const float4*)(bias + n0 + tx * 4);
#pragma unroll
    for (int i = 0; i < 8; i++) {
        float4 o;
        o.x = acc[i][0] + bv.x;
        o.y = acc[i][1] + bv.y;
        o.z = acc[i][2] + bv.z;
        o.w = acc[i][3] + bv.w;
        *(float4*)(Y + (long)(m0 + ty * 8 + i) * N + n0 + tx * 4) = o;
    }
}

// ----------------------------------------------------------------------------
// Flash attention, fp32, causal. One CTA per (b, h, 64-row q tile).
// 256 threads as 16x16 grid; each thread owns 4 q-rows x 4 cols.
// ----------------------------------------------------------------------------
#define PST 68                         // padded row stride (floats), 16B-aligned
#define SMEM_ATTN ((3 * 64 * PST + 64 * 64) * 4)

__global__ __launch_bounds__(256, 1) void attn_kernel()
{
    extern __shared__ float sm[];
    float* QsT = sm;                   // [64 d][PST rows]
    float* KsT = sm + 64 * PST;        // [64 d][PST kcols]
    float* PsT = sm + 2 * 64 * PST;    // [64 k][PST rows]
    float* Vs  = sm + 3 * 64 * PST;    // [64 k][64 d]

    const int tid = threadIdx.x;
    const int qt  = (int)(gridDim.x - 1 - blockIdx.x);  // heavy tiles first
    const int h   = blockIdx.y;
    const int b   = blockIdx.z;
    const int q0  = qt * 64;
    const int tx  = tid & 15;          // score k-col group / output d group
    const int ty  = tid >> 4;          // q-row group

    const float* Qb = g_Q + ((long)b * SEQ) * D_MODEL + h * DK;
    const float* Kb = g_K + ((long)b * SEQ) * D_MODEL + h * DK;
    const float* Vb = g_V + ((long)b * SEQ) * D_MODEL + h * DK;
    float*       Xb = g_X + ((long)b * SEQ) * D_MODEL + h * DK;

    // Load Q tile transposed: QsT[d][r]
#pragma unroll
    for (int t = 0; t < 4; t++) {
        int i = tid + t * 256;         // 1024 float4s total for 64x64
        int r = i >> 4;                // 0..63
        int d4 = (i & 15) << 2;        // 0..60
        float4 v = *(const float4*)(Qb + (long)(q0 + r) * D_MODEL + d4);
        QsT[(d4 + 0) * PST + r] = v.x;
        QsT[(d4 + 1) * PST + r] = v.y;
        QsT[(d4 + 2) * PST + r] = v.z;
        QsT[(d4 + 3) * PST + r] = v.w;
    }

    float m_i[4], l_i[4], o[4][4];
#pragma unroll
    for (int i = 0; i < 4; i++) {
        m_i[i] = -1e30f; l_i[i] = 0.f;
#pragma unroll
        for (int j = 0; j < 4; j++) o[i][j] = 0.f;
    }

    const int nkt = qt + 1;            // causal: only k-tiles with k0 <= q0
    for (int kt = 0; kt < nkt; kt++) {
        const int k0 = kt * 64;
        __syncthreads();               // guard smem reuse (also covers Q load)
#pragma unroll
        for (int t = 0; t < 4; t++) {
            int i = tid + t * 256;
            int r = i >> 4;
            int d4 = (i & 15) << 2;
            float4 kv = *(const float4*)(Kb + (long)(k0 + r) * D_MODEL + d4);
            KsT[(d4 + 0) * PST + r] = kv.x;
            KsT[(d4 + 1) * PST + r] = kv.y;
            KsT[(d4 + 2) * PST + r] = kv.z;
            KsT[(d4 + 3) * PST + r] = kv.w;
            float4 vv = *(const float4*)(Vb + (long)(k0 + r) * D_MODEL + d4);
            *(float4*)&Vs[r * 64 + d4] = vv;
        }
        __syncthreads();

        // Scores: s[i][j] = Q[q0+ty*4+i] . K[k0+tx*4+j]
        float s[4][4];
#pragma unroll
        for (int i = 0; i < 4; i++)
#pragma unroll
            for (int j = 0; j < 4; j++) s[i][j] = 0.f;
#pragma unroll 8
        for (int d = 0; d < DK; d++) {
            float4 qa = *(const float4*)&QsT[d * PST + ty * 4];
            float4 kb = *(const float4*)&KsT[d * PST + tx * 4];
            s[0][0] = fmaf(qa.x, kb.x, s[0][0]); s[0][1] = fmaf(qa.x, kb.y, s[0][1]);
            s[0][2] = fmaf(qa.x, kb.z, s[0][2]); s[0][3] = fmaf(qa.x, kb.w, s[0][3]);
            s[1][0] = fmaf(qa.y, kb.x, s[1][0]); s[1][1] = fmaf(qa.y, kb.y, s[1][1]);
            s[1][2] = fmaf(qa.y, kb.z, s[1][2]); s[1][3] = fmaf(qa.y, kb.w, s[1][3]);
            s[2][0] = fmaf(qa.z, kb.x, s[2][0]); s[2][1] = fmaf(qa.z, kb.y, s[2][1]);
            s[2][2] = fmaf(qa.z, kb.z, s[2][2]); s[2][3] = fmaf(qa.z, kb.w, s[2][3]);
            s[3][0] = fmaf(qa.w, kb.x, s[3][0]); s[3][1] = fmaf(qa.w, kb.y, s[3][1]);
            s[3][2] = fmaf(qa.w, kb.z, s[3][2]); s[3][3] = fmaf(qa.w, kb.w, s[3][3]);
        }

        const float scale = 0.125f;    // 1/sqrt(64)
#pragma unroll
        for (int i = 0; i < 4; i++)
#pragma unroll
            for (int j = 0; j < 4; j++) s[i][j] *= scale;

        if (kt == qt) {                // only the diagonal tile is partial
#pragma unroll
            for (int i = 0; i < 4; i++) {
                int qr = ty * 4 + i;
#pragma unroll
                for (int j = 0; j < 4; j++)
                    if (tx * 4 + j > qr) s[i][j] = -1e30f;
            }
        }

        // Online softmax per q-row (16-thread row group via shfl width 16)
#pragma unroll
        for (int i = 0; i < 4; i++) {
            float t0 = fmaxf(fmaxf(s[i][0], s[i][1]), fmaxf(s[i][2], s[i][3]));
#pragma unroll
            for (int off = 8; off > 0; off >>= 1)
                t0 = fmaxf(t0, __shfl_xor_sync(0xffffffffu, t0, off, 16));
            float m_new = fmaxf(m_i[i], t0);
            float alpha = __expf(m_i[i] - m_new);
            float rs = 0.f;
#pragma unroll
            for (int j = 0; j < 4; j++) {
                s[i][j] = __expf(s[i][j] - m_new);
                rs += s[i][j];
            }
#pragma unroll
            for (int off = 8; off > 0; off >>= 1)
                rs += __shfl_xor_sync(0xffffffffu, rs, off, 16);
            l_i[i] = l_i[i] * alpha + rs;
#pragma unroll
            for (int j = 0; j < 4; j++) o[i][j] *= alpha;
            m_i[i] = m_new;
        }

        // Store P transposed: PsT[k][r]   (producer/consumer within same warp)
#pragma unroll
        for (int j = 0; j < 4; j++)
#pragma unroll
            for (int i = 0; i < 4; i++)
                PsT[(tx * 4 + j) * PST + ty * 4 + i] = s[i][j];
        __syncwarp();

        // O += P @ V
#pragma unroll 8
        for (int kk = 0; kk < 64; kk++) {
            float4 pa = *(const float4*)&PsT[kk * PST + ty * 4];
            float4 vb = *(const float4*)&Vs[kk * 64 + tx * 4];
            o[0][0] = fmaf(pa.x, vb.x, o[0][0]); o[0][1] = fmaf(pa.x, vb.y, o[0][1]);
            o[0][2] = fmaf(pa.x, vb.z, o[0][2]); o[0][3] = fmaf(pa.x, vb.w, o[0][3]);
            o[1][0] = fmaf(pa.y, vb.x, o[1][0]); o[1][1] = fmaf(pa.y, vb.y, o[1][1]);
            o[1][2] = fmaf(pa.y, vb.z, o[1][2]); o[1][3] = fmaf(pa.y, vb.w, o[1][3]);
            o[2][0] = fmaf(pa.z, vb.x, o[2][0]); o[2][1] = fmaf(pa.z, vb.y, o[2][1]);
            o[2][2] = fmaf(pa.z, vb.z, o[2][2]); o[2][3] = fmaf(pa.z, vb.w, o[2][3]);
            o[3][0] = fmaf(pa.w, vb.x, o[3][0]); o[3][1] = fmaf(pa.w, vb.y, o[3][1]);
            o[3][2] = fmaf(pa.w, vb.z, o[3][2]); o[3][3] = fmaf(pa.w, vb.w, o[3][3]);
        }
    }

    // Normalize + write x[b, s, h*64 + d]
#pragma unroll
    for (int i = 0; i < 4; i++) {
        float inv = 1.f / l_i[i];
        float4 ov;
        ov.x = o[i][0] * inv; ov.y = o[i][1] * inv;
        ov.z = o[i][2] * inv; ov.w = o[i][3] * inv;
        *(float4*)(Xb + (long)(q0 + ty * 4 + i) * D_MODEL + tx * 4) = ov;
    }
}

// ----------------------------------------------------------------------------
extern "C" void kernel_launch(void* const* d_in, const int* in_sizes, int n_in,
                              void* d_out, int out_size)
{
    const float* q   = (const float*)d_in[0];
    const float* k   = (const float*)d_in[1];
    const float* v   = (const float*)d_in[2];
    // d_in[3] = mask (int32 tril) — causal handled analytically
    const float* w_q = (const float*)d_in[4];
    const float* b_q = (const float*)d_in[5];
    const float* w_k = (const float*)d_in[6];
    const float* b_k = (const float*)d_in[7];
    const float* w_v = (const float*)d_in[8];
    const float* b_v = (const float*)d_in[9];
    const float* w_o = (const float*)d_in[10];
    const float* b_o = (const float*)d_in[11];
    float* out = (float*)d_out;

    float *pQ, *pK, *pV, *pX;
    cudaGetSymbolAddress((void**)&pQ, g_Q);
    cudaGetSymbolAddress((void**)&pK, g_K);
    cudaGetSymbolAddress((void**)&pV, g_V);
    cudaGetSymbolAddress((void**)&pX, g_X);

    dim3 ggrid(D_MODEL / BN, MROWS / BM);   // (16, 32)
    gemm_bias<<<ggrid, 256>>>(q, w_q, b_q, pQ, MROWS, D_MODEL, D_MODEL);
    gemm_bias<<<ggrid, 256>>>(k, w_k, b_k, pK, MROWS, D_MODEL, D_MODEL);
    gemm_bias<<<ggrid, 256>>>(v, w_v, b_v, pV, MROWS, D_MODEL, D_MODEL);

    cudaFuncSetAttribute(attn_kernel,
                         cudaFuncAttributeMaxDynamicSharedMemorySize, SMEM_ATTN);
    dim3 agrid(SEQ / 64, NHEADS, BATCH);    // (32, 16, 2)
    attn_kernel<<<agrid, 256, SMEM_ATTN>>>();

    gemm_bias<<<ggrid, 256>>>(pX, w_o, b_o, out, MROWS, D_MODEL, D_MODEL);
}

// round 4
// speedup vs baseline: 1.7612x; 1.7573x over previous
#include <cuda_runtime.h>
#include <cstdint>

#define D_MODEL 1024
#define NHEADS 16
#define DK 64
#define BATCH 2
#define SEQ 2048
#define MROWS (BATCH*SEQ)

// Scratch (allocation-free rule: __device__ globals)
__device__ float g_Q[MROWS * D_MODEL];
__device__ float g_K[MROWS * D_MODEL];
__device__ float g_V[MROWS * D_MODEL];
__device__ float g_X[MROWS * D_MODEL];

__device__ __forceinline__ uint32_t f2tf32(float x) {
    uint32_t r; asm("cvt.rna.tf32.f32 %0, %1;" : "=r"(r) : "f"(x)); return r;
}

// D += A(16x8,row) @ B(8x8,col)  — tf32 HMMA, base PTX (works on compute_103)
__device__ __forceinline__ void mma_tf32(float* d, const uint32_t* a, const uint32_t* b) {
    asm volatile(
        "mma.sync.aligned.m16n8k8.row.col.f32.tf32.tf32.f32 "
        "{%0,%1,%2,%3}, {%4,%5,%6,%7}, {%8,%9}, {%0,%1,%2,%3};"
        : "+f"(d[0]), "+f"(d[1]), "+f"(d[2]), "+f"(d[3])
        : "r"(a[0]), "r"(a[1]), "r"(a[2]), "r"(a[3]), "r"(b[0]), "r"(b[1]));
}

// ============================================================================
// tf32 mma.sync GEMM: Y[4096,1024] = X @ W^T + bias
// CTA tile 128x128, BK=32, 8 warps (2x4), warp tile 64x32.
// grid = (8, 32, nz); z selects one of 3 pointer sets (qkv fused launch)
// ============================================================================
#define GN 1024
#define GK 1024
#define TBM 128
#define TBN 128
#define TKC 32
#define NCHUNK (GK / TKC)
#define LDT 36                               // padded row stride (floats)
#define BUFSZ (TBM * LDT)                    // 4608 floats per matrix buffer
#define SM_GEMM_TOTAL (4 * BUFSZ * 4)        // A0,W0,A1,W1 = 73728 B

__global__ __launch_bounds__(256) void gemm_mma(
    const float* __restrict__ X0, const float* __restrict__ W0,
    const float* __restrict__ B0, float* __restrict__ Y0,
    const float* __restrict__ X1, const float* __restrict__ W1,
    const float* __restrict__ B1, float* __restrict__ Y1,
    const float* __restrict__ X2, const float* __restrict__ W2,
    const float* __restrict__ B2, float* __restrict__ Y2)
{
    extern __shared__ float sm[];
    const int tid  = threadIdx.x;
    const int lane = tid & 31;
    const int wid  = tid >> 5;
    const int gid  = lane >> 2;              // groupID 0..7
    const int tg   = lane & 3;               // thread-in-group 0..3
    const int wm   = (wid & 1) * 64;         // warp M offset in CTA tile
    const int wn   = (wid >> 1) * 32;        // warp N offset
    const int z    = blockIdx.z;

    const float* X    = (z == 0) ? X0 : (z == 1) ? X1 : X2;
    const float* W    = (z == 0) ? W0 : (z == 1) ? W1 : W2;
    const float* bias = (z == 0) ? B0 : (z == 1) ? B1 : B2;
    float*       Y    = (z == 0) ? Y0 : (z == 1) ? Y1 : Y2;

    const int m0 = blockIdx.y * TBM;
    const int n0 = blockIdx.x * TBN;

    // per-thread staging coordinates: 4 float4 per matrix per chunk
    const int srow = tid >> 3;               // 0..31 (advances by 32 per step)
    const int sc4  = (tid & 7) << 2;         // 0,4,...,28

    float acc[4][4][4];
#pragma unroll
    for (int i = 0; i < 4; i++)
#pragma unroll
        for (int j = 0; j < 4; j++)
#pragma unroll
            for (int r = 0; r < 4; r++) acc[i][j][r] = 0.f;

    float4 ra[4], rw[4];
    // LDG chunk 0
#pragma unroll
    for (int t = 0; t < 4; t++) {
        int row = srow + t * 32;
        ra[t] = *(const float4*)(X + (long)(m0 + row) * GK + sc4);
        rw[t] = *(const float4*)(W + (long)(n0 + row) * GK + sc4);
    }
    // cvt + STS chunk 0 into buf 0
    {
        float* As = sm;
        float* Ws = sm + BUFSZ;
#pragma unroll
        for (int t = 0; t < 4; t++) {
            int row = srow + t * 32;
            uint4 ta = make_uint4(f2tf32(ra[t].x), f2tf32(ra[t].y), f2tf32(ra[t].z), f2tf32(ra[t].w));
            *(uint4*)(As + row * LDT + sc4) = ta;
            uint4 tw = make_uint4(f2tf32(rw[t].x), f2tf32(rw[t].y), f2tf32(rw[t].z), f2tf32(rw[t].w));
            *(uint4*)(Ws + row * LDT + sc4) = tw;
        }
    }
    __syncthreads();

    for (int c = 0; c < NCHUNK; c++) {
        const int buf = c & 1;
        const uint32_t* As = (const uint32_t*)(sm + buf * 2 * BUFSZ);
        const uint32_t* Ws = As + BUFSZ;

        // issue LDG for next chunk early (hidden behind MMA work)
        if (c + 1 < NCHUNK) {
            const float* Xn = X + (c + 1) * TKC;
            const float* Wn = W + (c + 1) * TKC;
#pragma unroll
            for (int t = 0; t < 4; t++) {
                int row = srow + t * 32;
                ra[t] = *(const float4*)(Xn + (long)(m0 + row) * GK + sc4);
                rw[t] = *(const float4*)(Wn + (long)(n0 + row) * GK + sc4);
            }
        }

        // compute: 4 k-steps of m16n8k8
#pragma unroll
        for (int ks = 0; ks < 4; ks++) {
            const int kc = ks * 8 + tg;
            uint32_t af[4][4], bf[4][2];
#pragma unroll
            for (int i = 0; i < 4; i++) {
                int r = wm + i * 16 + gid;
                af[i][0] = As[r * LDT + kc];
                af[i][1] = As[(r + 8) * LDT + kc];
                af[i][2] = As[r * LDT + kc + 4];
                af[i][3] = As[(r + 8) * LDT + kc + 4];
            }
#pragma unroll
            for (int j = 0; j < 4; j++) {
                int n = wn + j * 8 + gid;
                bf[j][0] = Ws[n * LDT + kc];
                bf[j][1] = Ws[n * LDT + kc + 4];
            }
#pragma unroll
            for (int i = 0; i < 4; i++)
#pragma unroll
                for (int j = 0; j < 4; j++)
                    mma_tf32(acc[i][j], af[i], bf[j]);
        }

        if (c + 1 < NCHUNK) {
            __syncthreads();   // everyone done reading nbuf (chunk c-1)
            float* Ad = sm + (buf ^ 1) * 2 * BUFSZ;
            float* Wd = Ad + BUFSZ;
#pragma unroll
            for (int t = 0; t < 4; t++) {
                int row = srow + t * 32;
                uint4 ta = make_uint4(f2tf32(ra[t].x), f2tf32(ra[t].y), f2tf32(ra[t].z), f2tf32(ra[t].w));
                *(uint4*)(Ad + row * LDT + sc4) = ta;
                uint4 tw = make_uint4(f2tf32(rw[t].x), f2tf32(rw[t].y), f2tf32(rw[t].z), f2tf32(rw[t].w));
                *(uint4*)(Wd + row * LDT + sc4) = tw;
            }
            __syncthreads();
        }
    }

    // Epilogue: write accumulators + bias
#pragma unroll
    for (int i = 0; i < 4; i++) {
        const int r0 = m0 + wm + i * 16 + gid;
#pragma unroll
        for (int j = 0; j < 4; j++) {
            const int col = n0 + wn + j * 8 + tg * 2;
            float2 bv = *(const float2*)(bias + col);
            float2 o0, o1;
            o0.x = acc[i][j][0] + bv.x; o0.y = acc[i][j][1] + bv.y;
            o1.x = acc[i][j][2] + bv.x; o1.y = acc[i][j][3] + bv.y;
            *(float2*)(Y + (long)r0 * GN + col)       = o0;
            *(float2*)(Y + (long)(r0 + 8) * GN + col) = o1;
        }
    }
}

// ============================================================================
// Flash attention, fp32, causal. One CTA per (b, h, 64-row q tile). occ=2.
// ============================================================================
#define PST 68
#define SMEM_ATTN ((3 * 64 * PST + 64 * 64) * 4)

__global__ __launch_bounds__(256, 2) void attn_kernel()
{
    extern __shared__ float smf[];
    float* QsT = smf;
    float* KsT = smf + 64 * PST;
    float* PsT = smf + 2 * 64 * PST;
    float* Vs  = smf + 3 * 64 * PST;

    const int tid = threadIdx.x;
    const int qt  = (int)(gridDim.x - 1 - blockIdx.x);
    const int h   = blockIdx.y;
    const int b   = blockIdx.z;
    const int q0  = qt * 64;
    const int tx  = tid & 15;
    const int ty  = tid >> 4;

    const float* Qb = g_Q + ((long)b * SEQ) * D_MODEL + h * DK;
    const float* Kb = g_K + ((long)b * SEQ) * D_MODEL + h * DK;
    const float* Vb = g_V + ((long)b * SEQ) * D_MODEL + h * DK;
    float*       Xb = g_X + ((long)b * SEQ) * D_MODEL + h * DK;

#pragma unroll
    for (int t = 0; t < 4; t++) {
        int i = tid + t * 256;
        int r = i >> 4;
        int d4 = (i & 15) << 2;
        float4 v = *(const float4*)(Qb + (long)(q0 + r) * D_MODEL + d4);
        QsT[(d4 + 0) * PST + r] = v.x;
        QsT[(d4 + 1) * PST + r] = v.y;
        QsT[(d4 + 2) * PST + r] = v.z;
        QsT[(d4 + 3) * PST + r] = v.w;
    }

    float m_i[4], l_i[4], o[4][4];
#pragma unroll
    for (int i = 0; i < 4; i++) {
        m_i[i] = -1e30f; l_i[i] = 0.f;
#pragma unroll
        for (int j = 0; j < 4; j++) o[i][j] = 0.f;
    }

    const int nkt = qt + 1;
    for (int kt = 0; kt < nkt; kt++) {
        const int k0 = kt * 64;
        __syncthreads();
#pragma unroll
        for (int t = 0; t < 4; t++) {
            int i = tid + t * 256;
            int r = i >> 4;
            int d4 = (i & 15) << 2;
            float4 kv = *(const float4*)(Kb + (long)(k0 + r) * D_MODEL + d4);
            KsT[(d4 + 0) * PST + r] = kv.x;
            KsT[(d4 + 1) * PST + r] = kv.y;
            KsT[(d4 + 2) * PST + r] = kv.z;
            KsT[(d4 + 3) * PST + r] = kv.w;
            float4 vv = *(const float4*)(Vb + (long)(k0 + r) * D_MODEL + d4);
            *(float4*)&Vs[r * 64 + d4] = vv;
        }
        __syncthreads();

        float s[4][4];
#pragma unroll
        for (int i = 0; i < 4; i++)
#pragma unroll
            for (int j = 0; j < 4; j++) s[i][j] = 0.f;
#pragma unroll 8
        for (int d = 0; d < DK; d++) {
            float4 qa = *(const float4*)&QsT[d * PST + ty * 4];
            float4 kb = *(const float4*)&KsT[d * PST + tx * 4];
            s[0][0] = fmaf(qa.x, kb.x, s[0][0]); s[0][1] = fmaf(qa.x, kb.y, s[0][1]);
            s[0][2] = fmaf(qa.x, kb.z, s[0][2]); s[0][3] = fmaf(qa.x, kb.w, s[0][3]);
            s[1][0] = fmaf(qa.y, kb.x, s[1][0]); s[1][1] = fmaf(qa.y, kb.y, s[1][1]);
            s[1][2] = fmaf(qa.y, kb.z, s[1][2]); s[1][3] = fmaf(qa.y, kb.w, s[1][3]);
            s[2][0] = fmaf(qa.z, kb.x, s[2][0]); s[2][1] = fmaf(qa.z, kb.y, s[2][1]);
            s[2][2] = fmaf(qa.z, kb.z, s[2][2]); s[2][3] = fmaf(qa.z, kb.w, s[2][3]);
            s[3][0] = fmaf(qa.w, kb.x, s[3][0]); s[3][1] = fmaf(qa.w, kb.y, s[3][1]);
            s[3][2] = fmaf(qa.w, kb.z, s[3][2]); s[3][3] = fmaf(qa.w, kb.w, s[3][3]);
        }

        const float scale = 0.125f;
#pragma unroll
        for (int i = 0; i < 4; i++)
#pragma unroll
            for (int j = 0; j < 4; j++) s[i][j] *= scale;

        if (kt == qt) {
#pragma unroll
            for (int i = 0; i < 4; i++) {
                int qr = ty * 4 + i;
#pragma unroll
                for (int j = 0; j < 4; j++)
                    if (tx * 4 + j > qr) s[i][j] = -1e30f;
            }
        }

#pragma unroll
        for (int i = 0; i < 4; i++) {
            float t0 = fmaxf(fmaxf(s[i][0], s[i][1]), fmaxf(s[i][2], s[i][3]));
#pragma unroll
            for (int off = 8; off > 0; off >>= 1)
                t0 = fmaxf(t0, __shfl_xor_sync(0xffffffffu, t0, off, 16));
            float m_new = fmaxf(m_i[i], t0);
            float alpha = __expf(m_i[i] - m_new);
            float rs = 0.f;
#pragma unroll
            for (int j = 0; j < 4; j++) {
                s[i][j] = __expf(s[i][j] - m_new);
                rs += s[i][j];
            }
#pragma unroll
            for (int off = 8; off > 0; off >>= 1)
                rs += __shfl_xor_sync(0xffffffffu, rs, off, 16);
            l_i[i] = l_i[i] * alpha + rs;
#pragma unroll
            for (int j = 0; j < 4; j++) o[i][j] *= alpha;
            m_i[i] = m_new;
        }

#pragma unroll
        for (int j = 0; j < 4; j++)
#pragma unroll
            for (int i = 0; i < 4; i++)
                PsT[(tx * 4 + j) * PST + ty * 4 + i] = s[i][j];
        __syncwarp();

#pragma unroll 8
        for (int kk = 0; kk < 64; kk++) {
            float4 pa = *(const float4*)&PsT[kk * PST + ty * 4];
            float4 vb = *(const float4*)&Vs[kk * 64 + tx * 4];
            o[0][0] = fmaf(pa.x, vb.x, o[0][0]); o[0][1] = fmaf(pa.x, vb.y, o[0][1]);
            o[0][2] = fmaf(pa.x, vb.z, o[0][2]); o[0][3] = fmaf(pa.x, vb.w, o[0][3]);
            o[1][0] = fmaf(pa.y, vb.x, o[1][0]); o[1][1] = fmaf(pa.y, vb.y, o[1][1]);
            o[1][2] = fmaf(pa.y, vb.z, o[1][2]); o[1][3] = fmaf(pa.y, vb.w, o[1][3]);
            o[2][0] = fmaf(pa.z, vb.x, o[2][0]); o[2][1] = fmaf(pa.z, vb.y, o[2][1]);
            o[2][2] = fmaf(pa.z, vb.z, o[2][2]); o[2][3] = fmaf(pa.z, vb.w, o[2][3]);
            o[3][0] = fmaf(pa.w, vb.x, o[3][0]); o[3][1] = fmaf(pa.w, vb.y, o[3][1]);
            o[3][2] = fmaf(pa.w, vb.z, o[3][2]); o[3][3] = fmaf(pa.w, vb.w, o[3][3]);
        }
    }

#pragma unroll
    for (int i = 0; i < 4; i++) {
        float inv = 1.f / l_i[i];
        float4 ov;
        ov.x = o[i][0] * inv; ov.y = o[i][1] * inv;
        ov.z = o[i][2] * inv; ov.w = o[i][3] * inv;
        *(float4*)(Xb + (long)(q0 + ty * 4 + i) * D_MODEL + tx * 4) = ov;
    }
}

// ============================================================================
extern "C" void kernel_launch(void* const* d_in, const int* in_sizes, int n_in,
                              void* d_out, int out_size)
{
    const float* q   = (const float*)d_in[0];
    const float* k   = (const float*)d_in[1];
    const float* v   = (const float*)d_in[2];
    // d_in[3] = mask (int32 tril) — causal handled analytically
    const float* w_q = (const float*)d_in[4];
    const float* b_q = (const float*)d_in[5];
    const float* w_k = (const float*)d_in[6];
    const float* b_k = (const float*)d_in[7];
    const float* w_v = (const float*)d_in[8];
    const float* b_v = (const float*)d_in[9];
    const float* w_o = (const float*)d_in[10];
    const float* b_o = (const float*)d_in[11];
    float* out = (float*)d_out;

    float *pQ, *pK, *pV, *pX;
    cudaGetSymbolAddress((void**)&pQ, g_Q);
    cudaGetSymbolAddress((void**)&pK, g_K);
    cudaGetSymbolAddress((void**)&pV, g_V);
    cudaGetSymbolAddress((void**)&pX, g_X);

    cudaFuncSetAttribute(gemm_mma,
                         cudaFuncAttributeMaxDynamicSharedMemorySize, SM_GEMM_TOTAL);
    cudaFuncSetAttribute(attn_kernel,
                         cudaFuncAttributeMaxDynamicSharedMemorySize, SMEM_ATTN);

    // Fused q/k/v projections (z selects)
    dim3 qkv_grid(GN / TBN, MROWS / TBM, 3);      // (8, 32, 3)
    gemm_mma<<<qkv_grid, 256, SM_GEMM_TOTAL>>>(
        q, w_q, b_q, pQ,
        k, w_k, b_k, pK,
        v, w_v, b_v, pV);

    dim3 agrid(SEQ / 64, NHEADS, BATCH);          // (32, 16, 2)
    attn_kernel<<<agrid, 256, SMEM_ATTN>>>();

    // Output projection
    dim3 ogrid(GN / TBN, MROWS / TBM, 1);
    gemm_mma<<<ogrid, 256, SM_GEMM_TOTAL>>>(
        pX, w_o, b_o, out,
        pX, w_o, b_o, out,
        pX, w_o, b_o, out);
}

// round 5
// speedup vs baseline: 3.2405x; 1.8400x over previous
#include <cuda_runtime.h>
#include <cstdint>

#define D_MODEL 1024
#define NHEADS 16
#define DK 64
#define BATCH 2
#define SEQ 2048
#define MROWS (BATCH*SEQ)

// Scratch (allocation-free rule: __device__ globals)
__device__ float g_Q[MROWS * D_MODEL];
__device__ float g_K[MROWS * D_MODEL];
__device__ float g_V[MROWS * D_MODEL];
__device__ float g_X[MROWS * D_MODEL];

__device__ __forceinline__ uint32_t f2tf32(float x) {
    uint32_t r; asm("cvt.rna.tf32.f32 %0, %1;" : "=r"(r) : "f"(x)); return r;
}

// D += A(16x8,row) @ B(8x8,col)  — tf32 HMMA, base PTX (works on compute_103)
__device__ __forceinline__ void mma_tf32(float* d, const uint32_t* a, const uint32_t* b) {
    asm volatile(
        "mma.sync.aligned.m16n8k8.row.col.f32.tf32.tf32.f32 "
        "{%0,%1,%2,%3}, {%4,%5,%6,%7}, {%8,%9}, {%0,%1,%2,%3};"
        : "+f"(d[0]), "+f"(d[1]), "+f"(d[2]), "+f"(d[3])
        : "r"(a[0]), "r"(a[1]), "r"(a[2]), "r"(a[3]), "r"(b[0]), "r"(b[1]));
}

// ============================================================================
// tf32 mma.sync GEMM: Y[4096,1024] = X @ W^T + bias
// CTA tile 128x128, BK=32, 8 warps (2x4), warp tile 64x32.
// ============================================================================
#define GN 1024
#define GK 1024
#define TBM 128
#define TBN 128
#define TKC 32
#define NCHUNK (GK / TKC)
#define LDT 36
#define BUFSZ (TBM * LDT)
#define SM_GEMM_TOTAL (4 * BUFSZ * 4)

__global__ __launch_bounds__(256) void gemm_mma(
    const float* __restrict__ X0, const float* __restrict__ W0,
    const float* __restrict__ B0, float* __restrict__ Y0,
    const float* __restrict__ X1, const float* __restrict__ W1,
    const float* __restrict__ B1, float* __restrict__ Y1,
    const float* __restrict__ X2, const float* __restrict__ W2,
    const float* __restrict__ B2, float* __restrict__ Y2,
    int round_out)
{
    extern __shared__ float sm[];
    const int tid  = threadIdx.x;
    const int lane = tid & 31;
    const int wid  = tid >> 5;
    const int gid  = lane >> 2;
    const int tg   = lane & 3;
    const int wm   = (wid & 1) * 64;
    const int wn   = (wid >> 1) * 32;
    const int z    = blockIdx.z;

    const float* X    = (z == 0) ? X0 : (z == 1) ? X1 : X2;
    const float* W    = (z == 0) ? W0 : (z == 1) ? W1 : W2;
    const float* bias = (z == 0) ? B0 : (z == 1) ? B1 : B2;
    float*       Y    = (z == 0) ? Y0 : (z == 1) ? Y1 : Y2;

    const int m0 = blockIdx.y * TBM;
    const int n0 = blockIdx.x * TBN;

    const int srow = tid >> 3;
    const int sc4  = (tid & 7) << 2;

    float acc[4][4][4];
#pragma unroll
    for (int i = 0; i < 4; i++)
#pragma unroll
        for (int j = 0; j < 4; j++)
#pragma unroll
            for (int r = 0; r < 4; r++) acc[i][j][r] = 0.f;

    float4 ra[4], rw[4];
#pragma unroll
    for (int t = 0; t < 4; t++) {
        int row = srow + t * 32;
        ra[t] = *(const float4*)(X + (long)(m0 + row) * GK + sc4);
        rw[t] = *(const float4*)(W + (long)(n0 + row) * GK + sc4);
    }
    {
        float* As = sm;
        float* Ws = sm + BUFSZ;
#pragma unroll
        for (int t = 0; t < 4; t++) {
            int row = srow + t * 32;
            uint4 ta = make_uint4(f2tf32(ra[t].x), f2tf32(ra[t].y), f2tf32(ra[t].z), f2tf32(ra[t].w));
            *(uint4*)(As + row * LDT + sc4) = ta;
            uint4 tw = make_uint4(f2tf32(rw[t].x), f2tf32(rw[t].y), f2tf32(rw[t].z), f2tf32(rw[t].w));
            *(uint4*)(Ws + row * LDT + sc4) = tw;
        }
    }
    __syncthreads();

    for (int c = 0; c < NCHUNK; c++) {
        const int buf = c & 1;
        const uint32_t* As = (const uint32_t*)(sm + buf * 2 * BUFSZ);
        const uint32_t* Ws = As + BUFSZ;

        if (c + 1 < NCHUNK) {
            const float* Xn = X + (c + 1) * TKC;
            const float* Wn = W + (c + 1) * TKC;
#pragma unroll
            for (int t = 0; t < 4; t++) {
                int row = srow + t * 32;
                ra[t] = *(const float4*)(Xn + (long)(m0 + row) * GK + sc4);
                rw[t] = *(const float4*)(Wn + (long)(n0 + row) * GK + sc4);
            }
        }

#pragma unroll
        for (int ks = 0; ks < 4; ks++) {
            const int kc = ks * 8 + tg;
            uint32_t af[4][4], bf[4][2];
#pragma unroll
            for (int i = 0; i < 4; i++) {
                int r = wm + i * 16 + gid;
                af[i][0] = As[r * LDT + kc];
                af[i][1] = As[(r + 8) * LDT + kc];
                af[i][2] = As[r * LDT + kc + 4];
                af[i][3] = As[(r + 8) * LDT + kc + 4];
            }
#pragma unroll
            for (int j = 0; j < 4; j++) {
                int n = wn + j * 8 + gid;
                bf[j][0] = Ws[n * LDT + kc];
                bf[j][1] = Ws[n * LDT + kc + 4];
            }
#pragma unroll
            for (int i = 0; i < 4; i++)
#pragma unroll
                for (int j = 0; j < 4; j++)
                    mma_tf32(acc[i][j], af[i], bf[j]);
        }

        if (c + 1 < NCHUNK) {
            __syncthreads();
            float* Ad = sm + (buf ^ 1) * 2 * BUFSZ;
            float* Wd = Ad + BUFSZ;
#pragma unroll
            for (int t = 0; t < 4; t++) {
                int row = srow + t * 32;
                uint4 ta = make_uint4(f2tf32(ra[t].x), f2tf32(ra[t].y), f2tf32(ra[t].z), f2tf32(ra[t].w));
                *(uint4*)(Ad + row * LDT + sc4) = ta;
                uint4 tw = make_uint4(f2tf32(rw[t].x), f2tf32(rw[t].y), f2tf32(rw[t].z), f2tf32(rw[t].w));
                *(uint4*)(Wd + row * LDT + sc4) = tw;
            }
            __syncthreads();
        }
    }

    // Epilogue (optionally pre-round outputs to tf32 for the attention stage)
#pragma unroll
    for (int i = 0; i < 4; i++) {
        const int r0 = m0 + wm + i * 16 + gid;
#pragma unroll
        for (int j = 0; j < 4; j++) {
            const int col = n0 + wn + j * 8 + tg * 2;
            float2 bv = *(const float2*)(bias + col);
            float2 o0, o1;
            o0.x = acc[i][j][0] + bv.x; o0.y = acc[i][j][1] + bv.y;
            o1.x = acc[i][j][2] + bv.x; o1.y = acc[i][j][3] + bv.y;
            if (round_out) {
                o0.x = __uint_as_float(f2tf32(o0.x));
                o0.y = __uint_as_float(f2tf32(o0.y));
                o1.x = __uint_as_float(f2tf32(o1.x));
                o1.y = __uint_as_float(f2tf32(o1.y));
            }
            *(float2*)(Y + (long)r0 * GN + col)       = o0;
            *(float2*)(Y + (long)(r0 + 8) * GN + col) = o1;
        }
    }
}

// ============================================================================
// Flash attention on mma.sync tf32. CTA: 128 q-rows x (b,h); 8 warps,
// each warp owns 16 q-rows x full 64 cols. K-tile = 64.
// ============================================================================
#define QT 128
#define KT 64
#define LQ 68
#define LK 68
#define LV 72
#define OFF_K (QT * LQ)                    // 8704
#define OFF_V (OFF_K + KT * LK)            // 13056
#define OFF_P (OFF_V + KT * LV)            // 17664
#define PWSZ  (16 * LQ)                    // per-warp P buffer
#define SMEM_ATTN2 ((OFF_P + 8 * PWSZ) * 4)  // 105472 B

__global__ __launch_bounds__(256) void attn_mma()
{
    extern __shared__ float sm[];
    float* Qs = sm;
    float* Ks = sm + OFF_K;
    float* Vs = sm + OFF_V;

    const int tid  = threadIdx.x;
    const int lane = tid & 31;
    const int wid  = tid >> 5;
    const int gid  = lane >> 2;
    const int tg   = lane & 3;
    const int wm   = wid * 16;
    float* Ps = sm + OFF_P + wid * PWSZ;

    const int qt = (int)(gridDim.x - 1 - blockIdx.x);  // heavy tiles first
    const int h  = blockIdx.y;
    const int b  = blockIdx.z;
    const int q0 = qt * QT;

    const float* Qb = g_Q + ((long)b * SEQ) * D_MODEL + h * DK;
    const float* Kb = g_K + ((long)b * SEQ) * D_MODEL + h * DK;
    const float* Vb = g_V + ((long)b * SEQ) * D_MODEL + h * DK;
    float*       Xb = g_X + ((long)b * SEQ) * D_MODEL + h * DK;

    // Load Q tile, folding softmax scale 1/8 (exact power of two; stays tf32)
#pragma unroll
    for (int t = 0; t < 8; t++) {
        int i = tid + t * 256;
        int r = i >> 4;
        int c4 = (i & 15) << 2;
        float4 v = *(const float4*)(Qb + (long)(q0 + r) * D_MODEL + c4);
        v.x *= 0.125f; v.y *= 0.125f; v.z *= 0.125f; v.w *= 0.125f;
        *(float4*)(Qs + r * LQ + c4) = v;
    }
    // Load K,V tile 0
#pragma unroll
    for (int t = 0; t < 4; t++) {
        int i = tid + t * 256;
        int r = i >> 4;
        int c4 = (i & 15) << 2;
        *(float4*)(Ks + r * LK + c4) = *(const float4*)(Kb + (long)r * D_MODEL + c4);
        *(float4*)(Vs + r * LV + c4) = *(const float4*)(Vb + (long)r * D_MODEL + c4);
    }
    __syncthreads();

    float m0r = -1e30f, m1r = -1e30f, l0 = 0.f, l1 = 0.f;
    float o[8][4];
#pragma unroll
    for (int j = 0; j < 8; j++)
#pragma unroll
        for (int r = 0; r < 4; r++) o[j][r] = 0.f;

    const int nkt = 2 * qt + 2;
    float4 rk[4], rv[4];

    for (int kt = 0; kt < nkt; kt++) {
        const int k0 = kt * KT;

        // prefetch next K/V tile into registers
        if (kt + 1 < nkt) {
            const int kn = (kt + 1) * KT;
#pragma unroll
            for (int t = 0; t < 4; t++) {
                int i = tid + t * 256;
                int r = i >> 4;
                int c4 = (i & 15) << 2;
                rk[t] = *(const float4*)(Kb + (long)(kn + r) * D_MODEL + c4);
                rv[t] = *(const float4*)(Vb + (long)(kn + r) * D_MODEL + c4);
            }
        }

        // S = Q @ K^T   (16 x 64 per warp)
        float s[8][4];
#pragma unroll
        for (int j = 0; j < 8; j++)
#pragma unroll
            for (int r = 0; r < 4; r++) s[j][r] = 0.f;

        const uint32_t* Qu = (const uint32_t*)Qs;
        const uint32_t* Ku = (const uint32_t*)Ks;
#pragma unroll
        for (int ks = 0; ks < 8; ks++) {
            const int kc = ks * 8 + tg;
            uint32_t af[4];
            af[0] = Qu[(wm + gid) * LQ + kc];
            af[1] = Qu[(wm + gid + 8) * LQ + kc];
            af[2] = Qu[(wm + gid) * LQ + kc + 4];
            af[3] = Qu[(wm + gid + 8) * LQ + kc + 4];
#pragma unroll
            for (int j = 0; j < 8; j++) {
                uint32_t bf[2];
                bf[0] = Ku[(j * 8 + gid) * LK + kc];
                bf[1] = Ku[(j * 8 + gid) * LK + kc + 4];
                mma_tf32(s[j], af, bf);
            }
        }

        // causal mask (only tiles overlapping the diagonal of this warp's rows)
        if (k0 + KT - 1 > q0 + wm) {
            const int r0 = q0 + wm + gid;
            const int r1 = r0 + 8;
#pragma unroll
            for (int j = 0; j < 8; j++) {
                const int c = k0 + j * 8 + 2 * tg;
                if (c     > r0) s[j][0] = -1e30f;
                if (c + 1 > r0) s[j][1] = -1e30f;
                if (c     > r1) s[j][2] = -1e30f;
                if (c + 1 > r1) s[j][3] = -1e30f;
            }
        }

        // online softmax: row0 = gid, row1 = gid+8; cols split across quad lanes
        {
            float t0 = -1e30f, t1 = -1e30f;
#pragma unroll
            for (int j = 0; j < 8; j++) {
                t0 = fmaxf(t0, fmaxf(s[j][0], s[j][1]));
                t1 = fmaxf(t1, fmaxf(s[j][2], s[j][3]));
            }
            t0 = fmaxf(t0, __shfl_xor_sync(0xffffffffu, t0, 1));
            t0 = fmaxf(t0, __shfl_xor_sync(0xffffffffu, t0, 2));
            t1 = fmaxf(t1, __shfl_xor_sync(0xffffffffu, t1, 1));
            t1 = fmaxf(t1, __shfl_xor_sync(0xffffffffu, t1, 2));
            const float mn0 = fmaxf(m0r, t0);
            const float mn1 = fmaxf(m1r, t1);
            const float a0 = __expf(m0r - mn0);
            const float a1 = __expf(m1r - mn1);
            float rs0 = 0.f, rs1 = 0.f;
#pragma unroll
            for (int j = 0; j < 8; j++) {
                s[j][0] = __expf(s[j][0] - mn0);
                s[j][1] = __expf(s[j][1] - mn0);
                s[j][2] = __expf(s[j][2] - mn1);
                s[j][3] = __expf(s[j][3] - mn1);
                rs0 += s[j][0] + s[j][1];
                rs1 += s[j][2] + s[j][3];
            }
            rs0 += __shfl_xor_sync(0xffffffffu, rs0, 1);
            rs0 += __shfl_xor_sync(0xffffffffu, rs0, 2);
            rs1 += __shfl_xor_sync(0xffffffffu, rs1, 1);
            rs1 += __shfl_xor_sync(0xffffffffu, rs1, 2);
            l0 = l0 * a0 + rs0;
            l1 = l1 * a1 + rs1;
            m0r = mn0; m1r = mn1;
#pragma unroll
            for (int j = 0; j < 8; j++) {
                o[j][0] *= a0; o[j][1] *= a0;
                o[j][2] *= a1; o[j][3] *= a1;
            }
        }

        // P -> smem (rna to tf32), C-fragment -> A-fragment relayout
#pragma unroll
        for (int j = 0; j < 8; j++) {
            float2 p0, p1;
            p0.x = __uint_as_float(f2tf32(s[j][0]));
            p0.y = __uint_as_float(f2tf32(s[j][1]));
            p1.x = __uint_as_float(f2tf32(s[j][2]));
            p1.y = __uint_as_float(f2tf32(s[j][3]));
            *(float2*)&Ps[gid * LQ + j * 8 + 2 * tg]       = p0;
            *(float2*)&Ps[(gid + 8) * LQ + j * 8 + 2 * tg] = p1;
        }
        __syncwarp();

        // O += P @ V
        const uint32_t* Pu = (const uint32_t*)Ps;
        const uint32_t* Vu = (const uint32_t*)Vs;
#pragma unroll
        for (int ks = 0; ks < 8; ks++) {
            const int kc = ks * 8 + tg;
            uint32_t af[4];
            af[0] = Pu[gid * LQ + kc];
            af[1] = Pu[(gid + 8) * LQ + kc];
            af[2] = Pu[gid * LQ + kc + 4];
            af[3] = Pu[(gid + 8) * LQ + kc + 4];
#pragma unroll
            for (int j = 0; j < 8; j++) {
                uint32_t bf[2];
                bf[0] = Vu[kc * LV + j * 8 + gid];
                bf[1] = Vu[(kc + 4) * LV + j * 8 + gid];
                mma_tf32(o[j], af, bf);
            }
        }

        __syncthreads();
        if (kt + 1 < nkt) {
#pragma unroll
            for (int t = 0; t < 4; t++) {
                int i = tid + t * 256;
                int r = i >> 4;
                int c4 = (i & 15) << 2;
                *(float4*)(Ks + r * LK + c4) = rk[t];
                *(float4*)(Vs + r * LV + c4) = rv[t];
            }
            __syncthreads();
        }
    }

    // normalize + write
    const float inv0 = 1.f / l0;
    const float inv1 = 1.f / l1;
    const int r0 = q0 + wm + gid;
#pragma unroll
    for (int j = 0; j < 8; j++) {
        const int col = j * 8 + 2 * tg;
        float2 o0, o1;
        o0.x = o[j][0] * inv0; o0.y = o[j][1] * inv0;
        o1.x = o[j][2] * inv1; o1.y = o[j][3] * inv1;
        *(float2*)(Xb + (long)r0 * D_MODEL + col)       = o0;
        *(float2*)(Xb + (long)(r0 + 8) * D_MODEL + col) = o1;
    }
}

// ============================================================================
extern "C" void kernel_launch(void* const* d_in, const int* in_sizes, int n_in,
                              void* d_out, int out_size)
{
    const float* q   = (const float*)d_in[0];
    const float* k   = (const float*)d_in[1];
    const float* v   = (const float*)d_in[2];
    // d_in[3] = mask (int32 tril) — causal handled analytically
    const float* w_q = (const float*)d_in[4];
    const float* b_q = (const float*)d_in[5];
    const float* w_k = (const float*)d_in[6];
    const float* b_k = (const float*)d_in[7];
    const float* w_v = (const float*)d_in[8];
    const float* b_v = (const float*)d_in[9];
    const float* w_o = (const float*)d_in[10];
    const float* b_o = (const float*)d_in[11];
    float* out = (float*)d_out;

    float *pQ, *pK, *pV, *pX;
    cudaGetSymbolAddress((void**)&pQ, g_Q);
    cudaGetSymbolAddress((void**)&pK, g_K);
    cudaGetSymbolAddress((void**)&pV, g_V);
    cudaGetSymbolAddress((void**)&pX, g_X);

    cudaFuncSetAttribute(gemm_mma,
                         cudaFuncAttributeMaxDynamicSharedMemorySize, SM_GEMM_TOTAL);
    cudaFuncSetAttribute(attn_mma,
                         cudaFuncAttributeMaxDynamicSharedMemorySize, SMEM_ATTN2);

    // Fused q/k/v projections; outputs pre-rounded to tf32 for attention
    dim3 qkv_grid(GN / TBN, MROWS / TBM, 3);      // (8, 32, 3)
    gemm_mma<<<qkv_grid, 256, SM_GEMM_TOTAL>>>(
        q, w_q, b_q, pQ,
        k, w_k, b_k, pK,
        v, w_v, b_v, pV, 1);

    dim3 agrid(SEQ / QT, NHEADS, BATCH);          // (16, 16, 2)
    attn_mma<<<agrid, 256, SMEM_ATTN2>>>();

    // Output projection (full fp32 out)
    dim3 ogrid(GN / TBN, MROWS / TBM, 1);
    gemm_mma<<<ogrid, 256, SM_GEMM_TOTAL>>>(
        pX, w_o, b_o, out,
        pX, w_o, b_o, out,
        pX, w_o, b_o, out, 0);
}

// round 6
// speedup vs baseline: 3.4081x; 1.0517x over previous
#include <cuda_runtime.h>
#include <cstdint>

#define D_MODEL 1024
#define NHEADS 16
#define DK 64
#define BATCH 2
#define SEQ 2048
#define MROWS (BATCH*SEQ)

// Scratch (allocation-free rule: __device__ globals)
__device__ float g_Q[MROWS * D_MODEL];
__device__ float g_K[MROWS * D_MODEL];
__device__ float g_V[MROWS * D_MODEL];
__device__ float g_X[MROWS * D_MODEL];
// tf32-rounded copies of GEMM inputs
__device__ float g_rq[MROWS * D_MODEL];
__device__ float g_rk[MROWS * D_MODEL];
__device__ float g_rv[MROWS * D_MODEL];
__device__ float g_rwq[D_MODEL * D_MODEL];
__device__ float g_rwk[D_MODEL * D_MODEL];
__device__ float g_rwv[D_MODEL * D_MODEL];
__device__ float g_rwo[D_MODEL * D_MODEL];

__device__ __forceinline__ uint32_t f2tf32(float x) {
    uint32_t r; asm("cvt.rna.tf32.f32 %0, %1;" : "=r"(r) : "f"(x)); return r;
}

// D += A(16x8,row) @ B(8x8,col)  — tf32 HMMA, base PTX (works on compute_103)
__device__ __forceinline__ void mma_tf32(float* d, const uint32_t* a, const uint32_t* b) {
    asm volatile(
        "mma.sync.aligned.m16n8k8.row.col.f32.tf32.tf32.f32 "
        "{%0,%1,%2,%3}, {%4,%5,%6,%7}, {%8,%9}, {%0,%1,%2,%3};"
        : "+f"(d[0]), "+f"(d[1]), "+f"(d[2]), "+f"(d[3])
        : "r"(a[0]), "r"(a[1]), "r"(a[2]), "r"(a[3]), "r"(b[0]), "r"(b[1]));
}

__device__ __forceinline__ void cp16(uint32_t saddr, const void* g) {
    asm volatile("cp.async.cg.shared.global [%0], [%1], 16;" :: "r"(saddr), "l"(g));
}
#define CP_COMMIT() asm volatile("cp.async.commit_group;" ::: "memory")
#define CP_WAIT1()  asm volatile("cp.async.wait_group 1;" ::: "memory")
#define CP_WAIT0()  asm volatile("cp.async.wait_group 0;" ::: "memory")

// ============================================================================
// Pre-round inputs to tf32 (rna). z: 0..2 activations q,k,v; 3..6 weights.
// ============================================================================
#define NACT (MROWS * D_MODEL)
#define NWT  (D_MODEL * D_MODEL)

__global__ void round_pass(const float* q, const float* k, const float* v,
                           const float* wq, const float* wk, const float* wv,
                           const float* wo)
{
    const int z = blockIdx.y;
    const float* src;
    float* dst;
    int n;
    switch (z) {
        case 0: src = q;  dst = g_rq;  n = NACT; break;
        case 1: src = k;  dst = g_rk;  n = NACT; break;
        case 2: src = v;  dst = g_rv;  n = NACT; break;
        case 3: src = wq; dst = g_rwq; n = NWT; break;
        case 4: src = wk; dst = g_rwk; n = NWT; break;
        case 5: src = wv; dst = g_rwv; n = NWT; break;
        default: src = wo; dst = g_rwo; n = NWT; break;
    }
    int i = (blockIdx.x * blockDim.x + threadIdx.x) * 4;
    if (i >= n) return;
    float4 x = *(const float4*)(src + i);
    uint4 r = make_uint4(f2tf32(x.x), f2tf32(x.y), f2tf32(x.z), f2tf32(x.w));
    *(uint4*)(dst + i) = r;
}

// ============================================================================
// tf32 mma.sync GEMM with cp.async staging (inputs pre-rounded to tf32):
// Y[4096,1024] = X @ W^T + bias. CTA tile 128x128, BK=32, 8 warps (2x4).
// ============================================================================
#define GN 1024
#define GK 1024
#define TBM 128
#define TBN 128
#define TKC 32
#define NCHUNK (GK / TKC)
#define LDT 36
#define BUFSZ (TBM * LDT)
#define SM_GEMM_TOTAL (4 * BUFSZ * 4)

__device__ __forceinline__ void stage_cp(const float* X, const float* W,
                                         uint32_t sA, uint32_t sW,
                                         int srow, int sc4)
{
#pragma unroll
    for (int t = 0; t < 4; t++) {
        int row = srow + t * 32;
        cp16(sA + (uint32_t)((row * LDT + sc4) << 2), X + (long)row * GK + sc4);
        cp16(sW + (uint32_t)((row * LDT + sc4) << 2), W + (long)row * GK + sc4);
    }
}

__global__ __launch_bounds__(256, 2) void gemm_mma(
    const float* __restrict__ X0, const float* __restrict__ W0,
    const float* __restrict__ B0, float* __restrict__ Y0,
    const float* __restrict__ X1, const float* __restrict__ W1,
    const float* __restrict__ B1, float* __restrict__ Y1,
    const float* __restrict__ X2, const float* __restrict__ W2,
    const float* __restrict__ B2, float* __restrict__ Y2,
    int round_out)
{
    extern __shared__ float sm[];
    const uint32_t sb = (uint32_t)__cvta_generic_to_shared(sm);
    const int tid  = threadIdx.x;
    const int lane = tid & 31;
    const int wid  = tid >> 5;
    const int gid  = lane >> 2;
    const int tg   = lane & 3;
    const int wm   = (wid & 1) * 64;
    const int wn   = (wid >> 1) * 32;
    const int z    = blockIdx.z;

    const float* X    = (z == 0) ? X0 : (z == 1) ? X1 : X2;
    const float* W    = (z == 0) ? W0 : (z == 1) ? W1 : W2;
    const float* bias = (z == 0) ? B0 : (z == 1) ? B1 : B2;
    float*       Y    = (z == 0) ? Y0 : (z == 1) ? Y1 : Y2;

    const int m0 = blockIdx.y * TBM;
    const int n0 = blockIdx.x * TBN;
    const float* Xb = X + (long)m0 * GK;
    const float* Wb = W + (long)n0 * GK;

    const int srow = tid >> 3;
    const int sc4  = (tid & 7) << 2;

    float acc[4][4][4];
#pragma unroll
    for (int i = 0; i < 4; i++)
#pragma unroll
        for (int j = 0; j < 4; j++)
#pragma unroll
            for (int r = 0; r < 4; r++) acc[i][j][r] = 0.f;

    // prologue: stage chunk 0 into buf 0
    stage_cp(Xb, Wb, sb, sb + BUFSZ * 4, srow, sc4);
    CP_COMMIT();

    for (int c = 0; c < NCHUNK; c++) {
        const int buf = c & 1;
        if (c + 1 < NCHUNK) {
            const uint32_t off = (uint32_t)((buf ^ 1) * 2 * BUFSZ) * 4;
            stage_cp(Xb + (c + 1) * TKC, Wb + (c + 1) * TKC,
                     sb + off, sb + off + BUFSZ * 4, srow, sc4);
            CP_COMMIT();
            CP_WAIT1();
        } else {
            CP_WAIT0();
        }
        __syncthreads();

        const uint32_t* As = (const uint32_t*)(sm + buf * 2 * BUFSZ);
        const uint32_t* Ws = As + BUFSZ;
#pragma unroll
        for (int ks = 0; ks < 4; ks++) {
            const int kc = ks * 8 + tg;
            uint32_t af[4][4], bf[4][2];
#pragma unroll
            for (int i = 0; i < 4; i++) {
                int r = wm + i * 16 + gid;
                af[i][0] = As[r * LDT + kc];
                af[i][1] = As[(r + 8) * LDT + kc];
                af[i][2] = As[r * LDT + kc + 4];
                af[i][3] = As[(r + 8) * LDT + kc + 4];
            }
#pragma unroll
            for (int j = 0; j < 4; j++) {
                int n = wn + j * 8 + gid;
                bf[j][0] = Ws[n * LDT + kc];
                bf[j][1] = Ws[n * LDT + kc + 4];
            }
#pragma unroll
            for (int i = 0; i < 4; i++)
#pragma unroll
                for (int j = 0; j < 4; j++)
                    mma_tf32(acc[i][j], af[i], bf[j]);
        }
        __syncthreads();
    }

    // Epilogue (optionally pre-round outputs to tf32 for the attention stage)
#pragma unroll
    for (int i = 0; i < 4; i++) {
        const int r0 = m0 + wm + i * 16 + gid;
#pragma unroll
        for (int j = 0; j < 4; j++) {
            const int col = n0 + wn + j * 8 + tg * 2;
            float2 bv = *(const float2*)(bias + col);
            float2 o0, o1;
            o0.x = acc[i][j][0] + bv.x; o0.y = acc[i][j][1] + bv.y;
            o1.x = acc[i][j][2] + bv.x; o1.y = acc[i][j][3] + bv.y;
            if (round_out) {
                o0.x = __uint_as_float(f2tf32(o0.x));
                o0.y = __uint_as_float(f2tf32(o0.y));
                o1.x = __uint_as_float(f2tf32(o1.x));
                o1.y = __uint_as_float(f2tf32(o1.y));
            }
            *(float2*)(Y + (long)r0 * GN + col)       = o0;
            *(float2*)(Y + (long)(r0 + 8) * GN + col) = o1;
        }
    }
}

// ============================================================================
// Flash attention on mma.sync tf32. CTA: 128 q-rows x (b,h); 8 warps,
// each warp owns 16 q-rows x full 64 cols. K-tile = 64.
// ============================================================================
#define QT 128
#define KT 64
#define LQ 68
#define LK 68
#define LV 72
#define OFF_K (QT * LQ)
#define OFF_V (OFF_K + KT * LK)
#define OFF_P (OFF_V + KT * LV)
#define PWSZ  (16 * LQ)
#define SMEM_ATTN2 ((OFF_P + 8 * PWSZ) * 4)

__global__ __launch_bounds__(256) void attn_mma()
{
    extern __shared__ float sm[];
    float* Qs = sm;
    float* Ks = sm + OFF_K;
    float* Vs = sm + OFF_V;

    const int tid  = threadIdx.x;
    const int lane = tid & 31;
    const int wid  = tid >> 5;
    const int gid  = lane >> 2;
    const int tg   = lane & 3;
    const int wm   = wid * 16;
    float* Ps = sm + OFF_P + wid * PWSZ;

    const int qt = (int)(gridDim.x - 1 - blockIdx.x);
    const int h  = blockIdx.y;
    const int b  = blockIdx.z;
    const int q0 = qt * QT;

    const float* Qb = g_Q + ((long)b * SEQ) * D_MODEL + h * DK;
    const float* Kb = g_K + ((long)b * SEQ) * D_MODEL + h * DK;
    const float* Vb = g_V + ((long)b * SEQ) * D_MODEL + h * DK;
    float*       Xb = g_X + ((long)b * SEQ) * D_MODEL + h * DK;

    // Load Q tile, folding softmax scale 1/8 (exact power of two; stays tf32)
#pragma unroll
    for (int t = 0; t < 8; t++) {
        int i = tid + t * 256;
        int r = i >> 4;
        int c4 = (i & 15) << 2;
        float4 v = *(const float4*)(Qb + (long)(q0 + r) * D_MODEL + c4);
        v.x *= 0.125f; v.y *= 0.125f; v.z *= 0.125f; v.w *= 0.125f;
        *(float4*)(Qs + r * LQ + c4) = v;
    }
#pragma unroll
    for (int t = 0; t < 4; t++) {
        int i = tid + t * 256;
        int r = i >> 4;
        int c4 = (i & 15) << 2;
        *(float4*)(Ks + r * LK + c4) = *(const float4*)(Kb + (long)r * D_MODEL + c4);
        *(float4*)(Vs + r * LV + c4) = *(const float4*)(Vb + (long)r * D_MODEL + c4);
    }
    __syncthreads();

    float m0r = -1e30f, m1r = -1e30f, l0 = 0.f, l1 = 0.f;
    float o[8][4];
#pragma unroll
    for (int j = 0; j < 8; j++)
#pragma unroll
        for (int r = 0; r < 4; r++) o[j][r] = 0.f;

    const int nkt = 2 * qt + 2;
    float4 rk[4], rv[4];

    for (int kt = 0; kt < nkt; kt++) {
        const int k0 = kt * KT;

        if (kt + 1 < nkt) {
            const int kn = (kt + 1) * KT;
#pragma unroll
            for (int t = 0; t < 4; t++) {
                int i = tid + t * 256;
                int r = i >> 4;
                int c4 = (i & 15) << 2;
                rk[t] = *(const float4*)(Kb + (long)(kn + r) * D_MODEL + c4);
                rv[t] = *(const float4*)(Vb + (long)(kn + r) * D_MODEL + c4);
            }
        }

        // S = Q @ K^T
        float s[8][4];
#pragma unroll
        for (int j = 0; j < 8; j++)
#pragma unroll
            for (int r = 0; r < 4; r++) s[j][r] = 0.f;

        const uint32_t* Qu = (const uint32_t*)Qs;
        const uint32_t* Ku = (const uint32_t*)Ks;
#pragma unroll
        for (int ks = 0; ks < 8; ks++) {
            const int kc = ks * 8 + tg;
            uint32_t af[4];
            af[0] = Qu[(wm + gid) * LQ + kc];
            af[1] = Qu[(wm + gid + 8) * LQ + kc];
            af[2] = Qu[(wm + gid) * LQ + kc + 4];
            af[3] = Qu[(wm + gid + 8) * LQ + kc + 4];
#pragma unroll
            for (int j = 0; j < 8; j++) {
                uint32_t bf[2];
                bf[0] = Ku[(j * 8 + gid) * LK + kc];
                bf[1] = Ku[(j * 8 + gid) * LK + kc + 4];
                mma_tf32(s[j], af, bf);
            }
        }

        if (k0 + KT - 1 > q0 + wm) {
            const int r0 = q0 + wm + gid;
            const int r1 = r0 + 8;
#pragma unroll
            for (int j = 0; j < 8; j++) {
                const int c = k0 + j * 8 + 2 * tg;
                if (c     > r0) s[j][0] = -1e30f;
                if (c + 1 > r0) s[j][1] = -1e30f;
                if (c     > r1) s[j][2] = -1e30f;
                if (c + 1 > r1) s[j][3] = -1e30f;
            }
        }

        // online softmax
        {
            float t0 = -1e30f, t1 = -1e30f;
#pragma unroll
            for (int j = 0; j < 8; j++) {
                t0 = fmaxf(t0, fmaxf(s[j][0], s[j][1]));
                t1 = fmaxf(t1, fmaxf(s[j][2], s[j][3]));
            }
            t0 = fmaxf(t0, __shfl_xor_sync(0xffffffffu, t0, 1));
            t0 = fmaxf(t0, __shfl_xor_sync(0xffffffffu, t0, 2));
            t1 = fmaxf(t1, __shfl_xor_sync(0xffffffffu, t1, 1));
            t1 = fmaxf(t1, __shfl_xor_sync(0xffffffffu, t1, 2));
            const float mn0 = fmaxf(m0r, t0);
            const float mn1 = fmaxf(m1r, t1);
            const float a0 = __expf(m0r - mn0);
            const float a1 = __expf(m1r - mn1);
            float rs0 = 0.f, rs1 = 0.f;
#pragma unroll
            for (int j = 0; j < 8; j++) {
                s[j][0] = __expf(s[j][0] - mn0);
                s[j][1] = __expf(s[j][1] - mn0);
                s[j][2] = __expf(s[j][2] - mn1);
                s[j][3] = __expf(s[j][3] - mn1);
                rs0 += s[j][0] + s[j][1];
                rs1 += s[j][2] + s[j][3];
            }
            rs0 += __shfl_xor_sync(0xffffffffu, rs0, 1);
            rs0 += __shfl_xor_sync(0xffffffffu, rs0, 2);
            rs1 += __shfl_xor_sync(0xffffffffu, rs1, 1);
            rs1 += __shfl_xor_sync(0xffffffffu, rs1, 2);
            l0 = l0 * a0 + rs0;
            l1 = l1 * a1 + rs1;
            m0r = mn0; m1r = mn1;
#pragma unroll
            for (int j = 0; j < 8; j++) {
                o[j][0] *= a0; o[j][1] *= a0;
                o[j][2] *= a1; o[j][3] *= a1;
            }
        }

        // P -> smem (rna to tf32)
#pragma unroll
        for (int j = 0; j < 8; j++) {
            float2 p0, p1;
            p0.x = __uint_as_float(f2tf32(s[j][0]));
            p0.y = __uint_as_float(f2tf32(s[j][1]));
            p1.x = __uint_as_float(f2tf32(s[j][2]));
            p1.y = __uint_as_float(f2tf32(s[j][3]));
            *(float2*)&Ps[gid * LQ + j * 8 + 2 * tg]       = p0;
            *(float2*)&Ps[(gid + 8) * LQ + j * 8 + 2 * tg] = p1;
        }
        __syncwarp();

        // O += P @ V
        const uint32_t* Pu = (const uint32_t*)Ps;
        const uint32_t* Vu = (const uint32_t*)Vs;
#pragma unroll
        for (int ks = 0; ks < 8; ks++) {
            const int kc = ks * 8 + tg;
            uint32_t af[4];
            af[0] = Pu[gid * LQ + kc];
            af[1] = Pu[(gid + 8) * LQ + kc];
            af[2] = Pu[gid * LQ + kc + 4];
            af[3] = Pu[(gid + 8) * LQ + kc + 4];
#pragma unroll
            for (int j = 0; j < 8; j++) {
                uint32_t bf[2];
                bf[0] = Vu[kc * LV + j * 8 + gid];
                bf[1] = Vu[(kc + 4) * LV + j * 8 + gid];
                mma_tf32(o[j], af, bf);
            }
        }

        __syncthreads();
        if (kt + 1 < nkt) {
#pragma unroll
            for (int t = 0; t < 4; t++) {
                int i = tid + t * 256;
                int r = i >> 4;
                int c4 = (i & 15) << 2;
                *(float4*)(Ks + r * LK + c4) = rk[t];
                *(float4*)(Vs + r * LV + c4) = rv[t];
            }
            __syncthreads();
        }
    }

    // normalize + write (rounded to tf32: feeds the o-projection MMA)
    const float inv0 = 1.f / l0;
    const float inv1 = 1.f / l1;
    const int r0 = q0 + wm + gid;
#pragma unroll
    for (int j = 0; j < 8; j++) {
        const int col = j * 8 + 2 * tg;
        float2 o0, o1;
        o0.x = __uint_as_float(f2tf32(o[j][0] * inv0));
        o0.y = __uint_as_float(f2tf32(o[j][1] * inv0));
        o1.x = __uint_as_float(f2tf32(o[j][2] * inv1));
        o1.y = __uint_as_float(f2tf32(o[j][3] * inv1));
        *(float2*)(Xb + (long)r0 * D_MODEL + col)       = o0;
        *(float2*)(Xb + (long)(r0 + 8) * D_MODEL + col) = o1;
    }
}

// ============================================================================
extern "C" void kernel_launch(void* const* d_in, const int* in_sizes, int n_in,
                              void* d_out, int out_size)
{
    const float* q   = (const float*)d_in[0];
    const float* k   = (const float*)d_in[1];
    const float* v   = (const float*)d_in[2];
    // d_in[3] = mask (int32 tril) — causal handled analytically
    const float* w_q = (const float*)d_in[4];
    const float* b_q = (const float*)d_in[5];
    const float* w_k = (const float*)d_in[6];
    const float* b_k = (const float*)d_in[7];
    const float* w_v = (const float*)d_in[8];
    const float* b_v = (const float*)d_in[9];
    const float* w_o = (const float*)d_in[10];
    const float* b_o = (const float*)d_in[11];
    float* out = (float*)d_out;

    float *pQ, *pK, *pV, *pX;
    float *prq, *prk, *prv, *pwq, *pwk, *pwv, *pwo;
    cudaGetSymbolAddress((void**)&pQ, g_Q);
    cudaGetSymbolAddress((void**)&pK, g_K);
    cudaGetSymbolAddress((void**)&pV, g_V);
    cudaGetSymbolAddress((void**)&pX, g_X);
    cudaGetSymbolAddress((void**)&prq, g_rq);
    cudaGetSymbolAddress((void**)&prk, g_rk);
    cudaGetSymbolAddress((void**)&prv, g_rv);
    cudaGetSymbolAddress((void**)&pwq, g_rwq);
    cudaGetSymbolAddress((void**)&pwk, g_rwk);
    cudaGetSymbolAddress((void**)&pwv, g_rwv);
    cudaGetSymbolAddress((void**)&pwo, g_rwo);

    cudaFuncSetAttribute(gemm_mma,
                         cudaFuncAttributeMaxDynamicSharedMemorySize, SM_GEMM_TOTAL);
    cudaFuncSetAttribute(attn_mma,
                         cudaFuncAttributeMaxDynamicSharedMemorySize, SMEM_ATTN2);

    // Pre-round all GEMM inputs to tf32 (rna)
    dim3 rgrid(NACT / 4 / 256, 7);
    round_pass<<<rgrid, 256>>>(q, k, v, w_q, w_k, w_v, w_o);

    // Fused q/k/v projections; outputs rounded to tf32 for attention
    dim3 qkv_grid(GN / TBN, MROWS / TBM, 3);      // (8, 32, 3)
    gemm_mma<<<qkv_grid, 256, SM_GEMM_TOTAL>>>(
        prq, pwq, b_q, pQ,
        prk, pwk, b_k, pK,
        prv, pwv, b_v, pV, 1);

    dim3 agrid(SEQ / QT, NHEADS, BATCH);          // (16, 16, 2)
    attn_mma<<<agrid, 256, SMEM_ATTN2>>>();

    // Output projection (full fp32 out)
    dim3 ogrid(GN / TBN, MROWS / TBM, 1);
    gemm_mma<<<ogrid, 256, SM_GEMM_TOTAL>>>(
        pX, pwo, b_o, out,
        pX, pwo, b_o, out,
        pX, pwo, b_o, out, 0);
}